// round 1
// baseline (speedup 1.0000x reference)
#include <cuda_runtime.h>
#include <cstdint>

// Problem constants
#define G_    64
#define T_    8192
#define DIN_  2560
#define DOUT_ 1664
#define CAP_  256

// Tiling
#define BM 128
#define BN 128
#define BK 16
#define LDK  20    // As row stride in words ([BM][LDK]) -> conflict-free frag loads
#define LDBN 136   // Bs row stride in words ([BK][LDBN]) -> conflict-free frag loads
#define NK (DIN_ / BK)   // 160

__device__ int g_starts[G_ + 1];

__global__ void starts_kernel(const int* __restrict__ counts) {
    if (threadIdx.x == 0 && blockIdx.x == 0) {
        int s = 0;
        for (int g = 0; g < G_; ++g) { g_starts[g] = s; s += counts[g]; }
        g_starts[G_] = s;
    }
}

__device__ __forceinline__ uint32_t f2tf32(float f) {
    uint32_t u;
    asm("cvt.rna.tf32.f32 %0, %1;" : "=r"(u) : "f"(f));
    return u;
}

__device__ __forceinline__ void mma_tf32(float* c, const uint32_t* a, const uint32_t* b) {
    asm volatile(
        "mma.sync.aligned.m16n8k8.row.col.f32.tf32.tf32.f32 "
        "{%0,%1,%2,%3}, {%4,%5,%6,%7}, {%8,%9}, {%0,%1,%2,%3};\n"
        : "+f"(c[0]), "+f"(c[1]), "+f"(c[2]), "+f"(c[3])
        : "r"(a[0]), "r"(a[1]), "r"(a[2]), "r"(a[3]), "r"(b[0]), "r"(b[1]));
}

__global__ __launch_bounds__(256)
void grouped_gemm_kernel(const float* __restrict__ X, const float* __restrict__ W,
                         const int* __restrict__ counts, float* __restrict__ Y) {
    __shared__ uint32_t As[2][BM][LDK];    // 2*128*20*4  = 20480 B
    __shared__ uint32_t Bs[2][BK][LDBN];   // 2*16*136*4  = 17408 B

    const int g  = blockIdx.z;
    const int mt = blockIdx.y;
    const int nt = blockIdx.x;
    const int cnt = counts[g];
    if (mt * BM >= cnt) return;
    const int gstart = g_starts[g];

    const int tid  = threadIdx.x;
    const int lane = tid & 31;
    const int warp = tid >> 5;
    const int warpM = warp & 3;      // 4 warps along M
    const int warpN = warp >> 2;     // 2 warps along N
    const int tg  = lane >> 2;       // groupID  (0..7)
    const int tig = lane & 3;        // thread-in-group (0..3)
    const int m0 = warpM * 32;
    const int n0 = warpN * 64;

    // ---- global load mapping ----
    // A tile [BM][BK] as float4: v in {tid, tid+256}; row = v/4, kvec = v%4
    const int ar0 = tid >> 2;        // 0..63  (second row is ar0+64)
    const int akv = tid & 3;
    long long arow0 = (long long)gstart + mt * BM + ar0;
    long long arow1 = arow0 + 64;
    if (arow0 > T_ - 1) arow0 = T_ - 1;   // clamp: rows past count are garbage, never stored
    if (arow1 > T_ - 1) arow1 = T_ - 1;
    const float* Aptr0 = X + arow0 * DIN_ + akv * 4;
    const float* Aptr1 = X + arow1 * DIN_ + akv * 4;

    // B tile [BK][BN] as float4: v in {tid, tid+256}; k = v/32, nvec = v%32
    const int bk0 = tid >> 5;        // 0..7 (second k is bk0+8)
    const int bnv = tid & 31;
    const float* Bbase = W + (long long)g * DIN_ * DOUT_ + (long long)nt * BN + bnv * 4;

    float4 aR0, aR1, bR0, bR1;

    auto load_tile = [&](int kt) {
        aR0 = *(const float4*)(Aptr0 + kt * BK);
        aR1 = *(const float4*)(Aptr1 + kt * BK);
        bR0 = *(const float4*)(Bbase + (long long)(kt * BK + bk0) * DOUT_);
        bR1 = *(const float4*)(Bbase + (long long)(kt * BK + bk0 + 8) * DOUT_);
    };

    auto store_tile = [&](int buf) {
        uint4 v;
        v.x = f2tf32(aR0.x); v.y = f2tf32(aR0.y); v.z = f2tf32(aR0.z); v.w = f2tf32(aR0.w);
        *(uint4*)&As[buf][ar0][akv * 4] = v;
        v.x = f2tf32(aR1.x); v.y = f2tf32(aR1.y); v.z = f2tf32(aR1.z); v.w = f2tf32(aR1.w);
        *(uint4*)&As[buf][ar0 + 64][akv * 4] = v;
        v.x = f2tf32(bR0.x); v.y = f2tf32(bR0.y); v.z = f2tf32(bR0.z); v.w = f2tf32(bR0.w);
        *(uint4*)&Bs[buf][bk0][bnv * 4] = v;
        v.x = f2tf32(bR1.x); v.y = f2tf32(bR1.y); v.z = f2tf32(bR1.z); v.w = f2tf32(bR1.w);
        *(uint4*)&Bs[buf][bk0 + 8][bnv * 4] = v;
    };

    float acc[2][8][4];
    #pragma unroll
    for (int mf = 0; mf < 2; ++mf)
        #pragma unroll
        for (int nf = 0; nf < 8; ++nf)
            #pragma unroll
            for (int i = 0; i < 4; ++i) acc[mf][nf][i] = 0.0f;

    load_tile(0);
    store_tile(0);
    __syncthreads();

    int cur = 0;
    for (int kt = 0; kt < NK; ++kt) {
        if (kt + 1 < NK) load_tile(kt + 1);

        #pragma unroll
        for (int kk = 0; kk < BK; kk += 8) {
            uint32_t af[2][4];
            #pragma unroll
            for (int mf = 0; mf < 2; ++mf) {
                const int mr = m0 + mf * 16 + tg;
                af[mf][0] = As[cur][mr    ][kk + tig];
                af[mf][1] = As[cur][mr + 8][kk + tig];
                af[mf][2] = As[cur][mr    ][kk + 4 + tig];
                af[mf][3] = As[cur][mr + 8][kk + 4 + tig];
            }
            uint32_t bf[8][2];
            #pragma unroll
            for (int nf = 0; nf < 8; ++nf) {
                const int nc = n0 + nf * 8 + tg;
                bf[nf][0] = Bs[cur][kk + tig    ][nc];
                bf[nf][1] = Bs[cur][kk + 4 + tig][nc];
            }
            #pragma unroll
            for (int mf = 0; mf < 2; ++mf)
                #pragma unroll
                for (int nf = 0; nf < 8; ++nf)
                    mma_tf32(acc[mf][nf], af[mf], bf[nf]);
        }

        if (kt + 1 < NK) {
            store_tile(cur ^ 1);
            __syncthreads();
            cur ^= 1;
        }
    }

    // ---- epilogue: predicated float2 stores (cols are even -> 8B aligned) ----
    #pragma unroll
    for (int mf = 0; mf < 2; ++mf) {
        const int r0 = mt * BM + m0 + mf * 16 + tg;
        const int r1 = r0 + 8;
        #pragma unroll
        for (int nf = 0; nf < 8; ++nf) {
            const int col = nt * BN + n0 + nf * 8 + tig * 2;
            if (r0 < cnt) {
                float2 v = make_float2(acc[mf][nf][0], acc[mf][nf][1]);
                *(float2*)&Y[(long long)(gstart + r0) * DOUT_ + col] = v;
            }
            if (r1 < cnt) {
                float2 v = make_float2(acc[mf][nf][2], acc[mf][nf][3]);
                *(float2*)&Y[(long long)(gstart + r1) * DOUT_ + col] = v;
            }
        }
    }
}

extern "C" void kernel_launch(void* const* d_in, const int* in_sizes, int n_in,
                              void* d_out, int out_size) {
    const float* x    = (const float*)d_in[0];
    const float* w    = (const float*)d_in[1];
    const int*   cnts = (const int*)d_in[2];
    float* y = (float*)d_out;

    starts_kernel<<<1, 32>>>(cnts);

    dim3 grid(DOUT_ / BN, CAP_ / BM, G_);   // (13, 2, 64)
    grouped_gemm_kernel<<<grid, 256>>>(x, w, cnts, y);
}

// round 4
// speedup vs baseline: 1.1607x; 1.1607x over previous
#include <cuda_runtime.h>
#include <cstdint>

// ---------------- problem constants ----------------
#define G_    64
#define T_    8192
#define DIN_  2560
#define DOUT_ 1664
#define CAP_  256

// ---------------- tiling ----------------
#define BM 64
#define BN 256
#define BK 16
#define NK (DIN_ / BK)        // 160
#define NT_N ((DOUT_ + BN - 1) / BN)   // 7 (last tile masked)

#define LDK  20               // A row stride in words (80B): ldmatrix conflict-free
#define LDBN 264              // B row stride in words (256 data + 8 pad)

#define A_WORDS (BM * LDK)    // 1280
#define B_WORDS (BK * LDBN)   // 4224

__device__ int g_starts[G_];

__global__ void starts_kernel(const int* __restrict__ counts) {
    if (threadIdx.x == 0 && blockIdx.x == 0) {
        int s = 0;
        for (int g = 0; g < G_; ++g) { g_starts[g] = s; s += counts[g]; }
    }
}

static __device__ __forceinline__ uint32_t smem_u32(const void* p) {
    uint32_t a;
    asm("{ .reg .u64 t; cvta.to.shared.u64 t, %1; cvt.u32.u64 %0, t; }" : "=r"(a) : "l"(p));
    return a;
}

static __device__ __forceinline__ uint32_t f2tf32(uint32_t rawf) {
    uint32_t u;
    asm("cvt.rna.tf32.f32 %0, %1;" : "=r"(u) : "r"(rawf));
    return u;
}

static __device__ __forceinline__ void cp16(uint32_t dst, const void* src) {
    asm volatile("cp.async.cg.shared.global [%0], [%1], 16;" :: "r"(dst), "l"(src));
}
#define CP_COMMIT()   asm volatile("cp.async.commit_group;")
#define CP_WAIT(n)    asm volatile("cp.async.wait_group %0;" :: "n"(n) : "memory")

#define LDSM4(r, a) \
    asm volatile("ldmatrix.sync.aligned.m8n8.x4.shared.b16 {%0,%1,%2,%3}, [%4];" \
        : "=r"((r)[0]), "=r"((r)[1]), "=r"((r)[2]), "=r"((r)[3]) : "r"(a))

static __device__ __forceinline__ void mma_tf32(float* c, const uint32_t* a,
                                                uint32_t b0, uint32_t b1) {
    asm volatile(
        "mma.sync.aligned.m16n8k8.row.col.f32.tf32.tf32.f32 "
        "{%0,%1,%2,%3}, {%4,%5,%6,%7}, {%8,%9}, {%0,%1,%2,%3};\n"
        : "+f"(c[0]), "+f"(c[1]), "+f"(c[2]), "+f"(c[3])
        : "r"(a[0]), "r"(a[1]), "r"(a[2]), "r"(a[3]), "r"(b0), "r"(b1));
}

__global__ __launch_bounds__(128, 2)
void grouped_gemm_kernel(const float* __restrict__ X, const float* __restrict__ W,
                         const int* __restrict__ counts, float* __restrict__ Y) {
    __shared__ uint32_t As[2][A_WORDS];   // [m][k], raw f32 bits, rows of 20 words
    __shared__ uint32_t Bs[2][B_WORDS];   // [k][n], raw f32 bits, rows of 264 words

    const int g  = blockIdx.z;
    const int mt = blockIdx.y;
    const int nt = blockIdx.x;
    const int cnt = counts[g];
    if (mt * BM >= cnt) return;
    const int gstart = g_starts[g];

    const int t    = threadIdx.x;
    const int lane = t & 31;
    const int wid  = t >> 5;             // 0..3, owns n-range wid*64
    const int tg   = lane >> 2;
    const int tig  = lane & 3;
    const int n0   = wid * 64;

    // ---- cp.async source/dest mapping ----
    // A: 2 chunks/thread: idx = t + 128*i -> row = idx>>2, kv = idx&3
    const int a_row = t >> 2;            // rows a_row, a_row+32
    const int a_kv  = t & 3;
    long long ar0 = (long long)gstart + mt * BM + a_row;
    long long ar1 = ar0 + 32;
    if (ar0 > T_ - 1) ar0 = T_ - 1;
    if (ar1 > T_ - 1) ar1 = T_ - 1;
    const float* Ag0 = X + ar0 * DIN_ + a_kv * 4;
    const float* Ag1 = X + ar1 * DIN_ + a_kv * 4;
    const uint32_t aDst0 = (uint32_t)((a_row      ) * LDK + a_kv * 4) * 4;
    const uint32_t aDst1 = (uint32_t)((a_row + 32) * LDK + a_kv * 4) * 4;

    // B: 8 chunks/thread: idx = t + 128*i -> k = idx>>6, nv = idx&63
    const int b_k0 = t >> 6;             // k = b_k0 + 2*i
    const int b_nv = t & 63;
    int bcol = nt * BN + b_nv * 4;       // clamp tail tile
    if (bcol > DOUT_ - 4) bcol = DOUT_ - 4;
    const float* Bg = W + (long long)g * DIN_ * DOUT_ + bcol;
    const uint32_t bDstBase = (uint32_t)(b_k0 * LDBN + b_nv * 4) * 4;

    const uint32_t sA = smem_u32(As);
    const uint32_t sB = smem_u32(Bs);

    auto issue_stage = [&](int kt) {
        const int buf = kt & 1;
        const uint32_t aB = sA + (uint32_t)buf * (A_WORDS * 4);
        const uint32_t bB = sB + (uint32_t)buf * (B_WORDS * 4);
        const int k0 = kt * BK;
        cp16(aB + aDst0, Ag0 + k0);
        cp16(aB + aDst1, Ag1 + k0);
        #pragma unroll
        for (int i = 0; i < 8; ++i)
            cp16(bB + bDstBase + (uint32_t)(2 * i * LDBN * 4),
                 Bg + (long long)(k0 + b_k0 + 2 * i) * DOUT_);
    };

    // ---- ldmatrix A addresses (byte offsets within one buffer) ----
    const int l15 = lane & 15;
    const int lhi = lane >> 4;
    uint32_t aoff[4];
    #pragma unroll
    for (int mf = 0; mf < 4; ++mf)
        aoff[mf] = (uint32_t)((mf * 16 + l15) * (LDK * 4) + lhi * 16);

    float acc[4][8][4];
    #pragma unroll
    for (int mf = 0; mf < 4; ++mf)
        #pragma unroll
        for (int nf = 0; nf < 8; ++nf)
            #pragma unroll
            for (int i = 0; i < 4; ++i) acc[mf][nf][i] = 0.0f;

    issue_stage(0);
    CP_COMMIT();

    for (int kt = 0; kt < NK; ++kt) {
        if (kt + 1 < NK) { issue_stage(kt + 1); CP_COMMIT(); CP_WAIT(1); }
        else             { CP_WAIT(0); }
        __syncthreads();                 // all warps' copies of stage kt visible

        const int buf = kt & 1;
        const uint32_t aB = sA + (uint32_t)buf * (A_WORDS * 4);
        const uint32_t bB = sB + (uint32_t)buf * (B_WORDS * 4);

        #pragma unroll
        for (int q = 0; q < 2; ++q) {
            uint32_t af[4][4];
            #pragma unroll
            for (int mf = 0; mf < 4; ++mf) {
                LDSM4(af[mf], aB + aoff[mf] + q * 32);
                af[mf][0] = f2tf32(af[mf][0]); af[mf][1] = f2tf32(af[mf][1]);
                af[mf][2] = f2tf32(af[mf][2]); af[mf][3] = f2tf32(af[mf][3]);
            }
            uint32_t bf[8][2];
            #pragma unroll
            for (int nf = 0; nf < 8; ++nf) {
                const uint32_t c = (uint32_t)(n0 + nf * 8 + tg) * 4;
                uint32_t v0, v1;
                asm volatile("ld.shared.b32 %0, [%1];" : "=r"(v0)
                             : "r"(bB + (uint32_t)((q * 8 + tig) * LDBN) * 4 + c));
                asm volatile("ld.shared.b32 %0, [%1];" : "=r"(v1)
                             : "r"(bB + (uint32_t)((q * 8 + 4 + tig) * LDBN) * 4 + c));
                bf[nf][0] = f2tf32(v0);
                bf[nf][1] = f2tf32(v1);
            }
            #pragma unroll
            for (int mf = 0; mf < 4; ++mf)
                #pragma unroll
                for (int nf = 0; nf < 8; ++nf)
                    mma_tf32(acc[mf][nf], af[mf], bf[nf][0], bf[nf][1]);
        }
        __syncthreads();                 // buffer kt free before stage kt+2 writes it
    }

    // ---- epilogue: predicated float2 stores ----
    #pragma unroll
    for (int mf = 0; mf < 4; ++mf) {
        const int r0 = mt * BM + mf * 16 + tg;
        const int r1 = r0 + 8;
        #pragma unroll
        for (int nf = 0; nf < 8; ++nf) {
            const int col = nt * BN + n0 + nf * 8 + tig * 2;
            if (col < DOUT_) {
                if (r0 < cnt) {
                    float2 v = make_float2(acc[mf][nf][0], acc[mf][nf][1]);
                    *(float2*)&Y[(long long)(gstart + r0) * DOUT_ + col] = v;
                }
                if (r1 < cnt) {
                    float2 v = make_float2(acc[mf][nf][2], acc[mf][nf][3]);
                    *(float2*)&Y[(long long)(gstart + r1) * DOUT_ + col] = v;
                }
            }
        }
    }
}

extern "C" void kernel_launch(void* const* d_in, const int* in_sizes, int n_in,
                              void* d_out, int out_size) {
    const float* x    = (const float*)d_in[0];
    const float* w    = (const float*)d_in[1];
    const int*   cnts = (const int*)d_in[2];
    float* y = (float*)d_out;

    starts_kernel<<<1, 32>>>(cnts);

    dim3 grid(NT_N, CAP_ / BM, G_);      // (7, 4, 64)
    grouped_gemm_kernel<<<grid, 128>>>(x, w, cnts, y);
}